// round 1
// baseline (speedup 1.0000x reference)
#include <cuda_runtime.h>
#include <math.h>

// Problem constants (fixed by setup_inputs)
#define BB   1024      // batch
#define LL   256       // latent dim
#define HH   512       // hidden
#define OO   128       // output size
#define TENC 200       // encoder length
#define SEQ  100       // decode steps (seq_len in setup_inputs)
#define H4   2048      // 4*H
#define K2H  1024      // 2*H  (concat [relu(x) | h])
#define BTENC (BB*TENC)

// ---------------- device scratch (static, allocation-free) ----------------
__device__ float g_Wcat[H4 * K2H];        // [4H, 2H] = [W_ih | W_hh]   (8 MB)
__device__ float g_bcat[H4];              // b_ih + b_hh
__device__ float g_emb[HH];               // emb_fc(start_token)  [H]
__device__ float g_xcat[2][BB * K2H];     // double-buffered [relu(x)|h] (2x4 MB)
__device__ float g_c[BB * HH];            // cell state (2 MB)
__device__ float g_h[(size_t)SEQ * BB * HH]; // h history (210 MB)

// ---------------- prep: build Wcat / bcat ----------------
__global__ void prep_kernel(const float* __restrict__ W_ih, const float* __restrict__ W_hh,
                            const float* __restrict__ b_ih, const float* __restrict__ b_hh) {
    int idx = blockIdx.x * blockDim.x + threadIdx.x;
    if (idx < H4 * K2H) {
        int n = idx / K2H, k = idx % K2H;
        g_Wcat[idx] = (k < HH) ? W_ih[n * HH + k] : W_hh[n * HH + (k - HH)];
    }
    if (idx < H4) g_bcat[idx] = b_ih[idx] + b_hh[idx];
}

// ---------------- emb: e = start_token @ W_emb^T + b_emb  (1 block, H threads) ----------------
__global__ void emb_kernel(const float* __restrict__ st, const float* __restrict__ W_emb,
                           const float* __restrict__ b_emb) {
    int j = threadIdx.x;
    float s = b_emb[j];
    #pragma unroll 8
    for (int k = 0; k < OO; k++) s += st[k] * W_emb[j * OO + k];
    g_emb[j] = s;
}

// ---------------- init: h0/c0 = lrelu(enc_hidden @ W^T + b); seed xcat[0], c ----------------
// Tile: BM=64 (m), BN=64 (j), BK=16. 256 threads, 4x4 frags for each of 2 matrices.
__global__ void __launch_bounds__(256) init_kernel(
    const float* __restrict__ eh, const float* __restrict__ W1, const float* __restrict__ b1,
    const float* __restrict__ W2, const float* __restrict__ b2) {
    __shared__ float As[64][17], B1s[64][17], B2s[64][17];
    int m0 = blockIdx.y * 64, j0 = blockIdx.x * 64;
    int tid = threadIdx.x, tm = tid >> 4, tj = tid & 15;
    float acc1[4][4] = {}, acc2[4][4] = {};
    for (int k0 = 0; k0 < LL; k0 += 16) {
        int r = tid >> 2, c = (tid & 3) * 4;
        float4 va = *(const float4*)&eh[(m0 + r) * LL + k0 + c];
        As[r][c] = va.x; As[r][c+1] = va.y; As[r][c+2] = va.z; As[r][c+3] = va.w;
        float4 v1 = *(const float4*)&W1[(j0 + r) * LL + k0 + c];
        B1s[r][c] = v1.x; B1s[r][c+1] = v1.y; B1s[r][c+2] = v1.z; B1s[r][c+3] = v1.w;
        float4 v2 = *(const float4*)&W2[(j0 + r) * LL + k0 + c];
        B2s[r][c] = v2.x; B2s[r][c+1] = v2.y; B2s[r][c+2] = v2.z; B2s[r][c+3] = v2.w;
        __syncthreads();
        #pragma unroll
        for (int kk = 0; kk < 16; kk++) {
            float a[4], u[4], v[4];
            #pragma unroll
            for (int i = 0; i < 4; i++) a[i] = As[tm * 4 + i][kk];
            #pragma unroll
            for (int jv = 0; jv < 4; jv++) { u[jv] = B1s[tj + jv * 16][kk]; v[jv] = B2s[tj + jv * 16][kk]; }
            #pragma unroll
            for (int i = 0; i < 4; i++)
                #pragma unroll
                for (int jv = 0; jv < 4; jv++) { acc1[i][jv] += a[i] * u[jv]; acc2[i][jv] += a[i] * v[jv]; }
        }
        __syncthreads();
    }
    #pragma unroll
    for (int i = 0; i < 4; i++)
        #pragma unroll
        for (int jv = 0; jv < 4; jv++) {
            int m = m0 + tm * 4 + i, j = j0 + tj + jv * 16;
            float h0 = acc1[i][jv] + b1[j]; h0 = h0 > 0.f ? h0 : 0.01f * h0;
            float c0 = acc2[i][jv] + b2[j]; c0 = c0 > 0.f ? c0 : 0.01f * c0;
            g_c[m * HH + j] = c0;
            g_xcat[0][m * K2H + HH + j] = h0;
            float e = g_emb[j];
            g_xcat[0][m * K2H + j] = e > 0.f ? e : 0.f;   // relu(x0)
        }
}

// ---------------- one LSTM step: fused GEMM (K=1024) + pointwise + state writes ----------------
// Block tile: 64 m-rows x 32 j-cols x 4 gates. Grid (H/32=16, B/64=16) = 256 blocks.
__global__ void __launch_bounds__(256) step_kernel(int t) {
    __shared__ float As[64][17];
    __shared__ float Bs[4][32][17];
    const float* __restrict__ xin = g_xcat[t & 1];
    float* __restrict__ xout = g_xcat[(t + 1) & 1];
    int j0 = blockIdx.x * 32, m0 = blockIdx.y * 64;
    int tid = threadIdx.x, tm = tid >> 4, tj = tid & 15;
    float acc[4][4][2] = {};
    for (int k0 = 0; k0 < K2H; k0 += 16) {
        {   // A tile 64x16 (1 float4/thread)
            int r = tid >> 2, c = (tid & 3) * 4;
            float4 v = *(const float4*)&xin[(m0 + r) * K2H + k0 + c];
            As[r][c] = v.x; As[r][c+1] = v.y; As[r][c+2] = v.z; As[r][c+3] = v.w;
        }
        #pragma unroll
        for (int q = 0; q < 2; q++) {   // B tiles: 4 gates x 32 x 16 (2 float4/thread)
            int idx = tid + q * 256;
            int gg = idx >> 7;                 // gate
            int r = (idx & 127) >> 2;          // 0..31
            int c = (idx & 3) * 4;
            float4 v = *(const float4*)&g_Wcat[(size_t)(gg * HH + j0 + r) * K2H + k0 + c];
            Bs[gg][r][c] = v.x; Bs[gg][r][c+1] = v.y; Bs[gg][r][c+2] = v.z; Bs[gg][r][c+3] = v.w;
        }
        __syncthreads();
        #pragma unroll
        for (int kk = 0; kk < 16; kk++) {
            float a[4];
            #pragma unroll
            for (int i = 0; i < 4; i++) a[i] = As[tm * 4 + i][kk];
            float bv[4][2];
            #pragma unroll
            for (int gg = 0; gg < 4; gg++) {
                bv[gg][0] = Bs[gg][tj][kk];
                bv[gg][1] = Bs[gg][tj + 16][kk];
            }
            #pragma unroll
            for (int gg = 0; gg < 4; gg++)
                #pragma unroll
                for (int i = 0; i < 4; i++)
                    #pragma unroll
                    for (int jv = 0; jv < 2; jv++)
                        acc[gg][i][jv] += a[i] * bv[gg][jv];
        }
        __syncthreads();
    }
    // Fused LSTM pointwise epilogue (pytorch gate order i,f,g,o)
    #pragma unroll
    for (int i = 0; i < 4; i++)
        #pragma unroll
        for (int jv = 0; jv < 2; jv++) {
            int m = m0 + tm * 4 + i, j = j0 + tj + jv * 16;
            float gi = acc[0][i][jv] + g_bcat[0 * HH + j];
            float gf = acc[1][i][jv] + g_bcat[1 * HH + j];
            float gg_ = acc[2][i][jv] + g_bcat[2 * HH + j];
            float go = acc[3][i][jv] + g_bcat[3 * HH + j];
            float iv = 1.f / (1.f + expf(-gi));
            float fv = 1.f / (1.f + expf(-gf));
            float gv = tanhf(gg_);
            float ov = 1.f / (1.f + expf(-go));
            float cn = fv * g_c[m * HH + j] + iv * gv;
            g_c[m * HH + j] = cn;
            float hn = ov * tanhf(cn);
            g_h[(size_t)t * (BB * HH) + m * HH + j] = hn;
            xout[m * K2H + j]      = hn > 0.f ? hn : 0.f;  // relu(x) side for next step
            xout[m * K2H + HH + j] = hn;                   // h side for next step
        }
}

// ---------------- output projection for all steps: y[t] = h[t] @ W_out^T + b_out ----------------
// Tile 64 m x 128 o, K=512. Grid (B/64=16, SEQ=100).
__global__ void __launch_bounds__(256) y_kernel(const float* __restrict__ W_out,
                                                const float* __restrict__ b_out,
                                                float* __restrict__ out_dec) {
    __shared__ float As[64][17];
    __shared__ float Bs[128][17];
    int t = blockIdx.y;
    int m0 = blockIdx.x * 64;
    int tid = threadIdx.x, tm = tid >> 4, to = tid & 15;
    const float* __restrict__ hsrc = &g_h[(size_t)t * (BB * HH)];
    float acc[4][8] = {};
    for (int k0 = 0; k0 < HH; k0 += 16) {
        {
            int r = tid >> 2, c = (tid & 3) * 4;
            float4 v = *(const float4*)&hsrc[(m0 + r) * HH + k0 + c];
            As[r][c] = v.x; As[r][c+1] = v.y; As[r][c+2] = v.z; As[r][c+3] = v.w;
        }
        #pragma unroll
        for (int q = 0; q < 2; q++) {
            int idx = tid + q * 256;
            int r = idx >> 2, c = (idx & 3) * 4;
            float4 v = *(const float4*)&W_out[r * HH + k0 + c];
            Bs[r][c] = v.x; Bs[r][c+1] = v.y; Bs[r][c+2] = v.z; Bs[r][c+3] = v.w;
        }
        __syncthreads();
        #pragma unroll
        for (int kk = 0; kk < 16; kk++) {
            float a[4], b[8];
            #pragma unroll
            for (int i = 0; i < 4; i++) a[i] = As[tm * 4 + i][kk];
            #pragma unroll
            for (int oi = 0; oi < 8; oi++) b[oi] = Bs[to + oi * 16][kk];
            #pragma unroll
            for (int i = 0; i < 4; i++)
                #pragma unroll
                for (int oi = 0; oi < 8; oi++) acc[i][oi] += a[i] * b[oi];
        }
        __syncthreads();
    }
    #pragma unroll
    for (int i = 0; i < 4; i++)
        #pragma unroll
        for (int oi = 0; oi < 8; oi++) {
            int m = m0 + tm * 4 + i, o = to + oi * 16;
            out_dec[((size_t)m * SEQ + t) * OO + o] = acc[i][oi] + b_out[o];
        }
}

// ---------------- copy hT / cT ----------------
__global__ void hc_kernel(float* __restrict__ out_h, float* __restrict__ out_c) {
    int i = blockIdx.x * blockDim.x + threadIdx.x;
    if (i < BB * HH) {
        out_h[i] = g_h[(size_t)(SEQ - 1) * (BB * HH) + i];
        out_c[i] = g_c[i];
    }
}

// ---------------- num head: relu(lrelu(E @ Wseq^T + b) @ w2 + b2), fully fused ----------------
// Block owns 64 rows; loops over all 8 j-tiles (N=512) internally; deterministic smem reduce.
__global__ void __launch_bounds__(256) num_kernel(
    const float* __restrict__ E, const float* __restrict__ Wseq, const float* __restrict__ bseq,
    const float* __restrict__ w2, const float* __restrict__ b2, float* __restrict__ outnum) {
    __shared__ float As[64][17], Bs[64][17];
    __shared__ float P[64][17];
    int m0 = blockIdx.x * 64;
    int tid = threadIdx.x, tm = tid >> 4, tj = tid & 15;
    float part[4] = {0.f, 0.f, 0.f, 0.f};
    for (int j0 = 0; j0 < HH; j0 += 64) {
        float acc[4][4] = {};
        for (int k0 = 0; k0 < LL; k0 += 16) {
            int r = tid >> 2, c = (tid & 3) * 4;
            float4 va = *(const float4*)&E[((size_t)(m0 + r)) * LL + k0 + c];
            As[r][c] = va.x; As[r][c+1] = va.y; As[r][c+2] = va.z; As[r][c+3] = va.w;
            float4 vb = *(const float4*)&Wseq[(j0 + r) * LL + k0 + c];
            Bs[r][c] = vb.x; Bs[r][c+1] = vb.y; Bs[r][c+2] = vb.z; Bs[r][c+3] = vb.w;
            __syncthreads();
            #pragma unroll
            for (int kk = 0; kk < 16; kk++) {
                float a[4], b[4];
                #pragma unroll
                for (int i = 0; i < 4; i++) a[i] = As[tm * 4 + i][kk];
                #pragma unroll
                for (int jv = 0; jv < 4; jv++) b[jv] = Bs[tj + jv * 16][kk];
                #pragma unroll
                for (int i = 0; i < 4; i++)
                    #pragma unroll
                    for (int jv = 0; jv < 4; jv++) acc[i][jv] += a[i] * b[jv];
            }
            __syncthreads();
        }
        #pragma unroll
        for (int i = 0; i < 4; i++)
            #pragma unroll
            for (int jv = 0; jv < 4; jv++) {
                int j = j0 + tj + jv * 16;
                float v = acc[i][jv] + bseq[j];
                v = v > 0.f ? v : 0.01f * v;   // leaky relu
                part[i] += v * w2[j];
            }
    }
    #pragma unroll
    for (int i = 0; i < 4; i++) P[tm * 4 + i][tj] = part[i];
    __syncthreads();
    if (tid < 64) {
        float s = 0.f;
        #pragma unroll
        for (int q = 0; q < 16; q++) s += P[tid][q];
        float v = s + b2[0];
        outnum[m0 + tid] = v > 0.f ? v : 0.f;
    }
}

// ---------------- launch ----------------
extern "C" void kernel_launch(void* const* d_in, const int* in_sizes, int n_in,
                              void* d_out, int out_size) {
    const float* enc_out = (const float*)d_in[0];   // [B, TENC, L]
    const float* enc_hid = (const float*)d_in[1];   // [B, L]
    const float* start   = (const float*)d_in[2];   // [1, O]
    const float* W1   = (const float*)d_in[3];      // W_lat2hid  [H, L]
    const float* b1   = (const float*)d_in[4];
    const float* W2   = (const float*)d_in[5];      // W_lat2hid2 [H, L]
    const float* b2   = (const float*)d_in[6];
    const float* Wemb = (const float*)d_in[7];      // [H, O]
    const float* bemb = (const float*)d_in[8];
    const float* Wih  = (const float*)d_in[9];      // [4H, H]
    const float* Whh  = (const float*)d_in[10];     // [4H, H]
    const float* bih  = (const float*)d_in[11];
    const float* bhh  = (const float*)d_in[12];
    const float* Wout = (const float*)d_in[13];     // [O, H]
    const float* bout = (const float*)d_in[14];
    const float* Wseq = (const float*)d_in[15];     // [H, L]
    const float* bseq = (const float*)d_in[16];
    const float* Wsq2 = (const float*)d_in[17];     // [1, H]
    const float* bsq2 = (const float*)d_in[18];
    // d_in[19] = seq_len (constant 100, unreadable during capture; hardcoded)

    float* out = (float*)d_out;
    float* out_dec = out;                                   // [B, SEQ, O]
    float* out_h   = out + (size_t)BB * SEQ * OO;           // [1, B, H]
    float* out_c   = out_h + (size_t)BB * HH;               // [1, B, H]
    float* out_num = out_c + (size_t)BB * HH;               // [B, TENC, 1]

    prep_kernel<<<(H4 * K2H + 255) / 256, 256>>>(Wih, Whh, bih, bhh);
    emb_kernel<<<1, HH>>>(start, Wemb, bemb);
    init_kernel<<<dim3(HH / 64, BB / 64), 256>>>(enc_hid, W1, b1, W2, b2);

    for (int t = 0; t < SEQ; t++)
        step_kernel<<<dim3(HH / 32, BB / 64), 256>>>(t);

    y_kernel<<<dim3(BB / 64, SEQ), 256>>>(Wout, bout, out_dec);
    hc_kernel<<<(BB * HH + 255) / 256, 256>>>(out_h, out_c);
    num_kernel<<<BTENC / 64, 256>>>(enc_out, Wseq, bseq, Wsq2, bsq2, out_num);
}

// round 3
// speedup vs baseline: 2.1724x; 2.1724x over previous
#include <cuda_runtime.h>
#include <cuda_bf16.h>
#include <math.h>
#include <stdint.h>

// Problem constants (fixed by setup_inputs)
#define BB   1024
#define LL   256
#define HH   512
#define OO   128
#define TENC 200
#define SEQ  100
#define H4   2048
#define K2H  1024
#define BTENC (BB*TENC)

// ======================= helpers =======================
__device__ __forceinline__ uint32_t smem_u32(const void* p) {
    uint32_t a;
    asm("{ .reg .u64 t; cvta.to.shared.u64 t, %1; cvt.u32.u64 %0, t; }" : "=r"(a) : "l"(p));
    return a;
}
__device__ __forceinline__ void ldm_x4(uint32_t* r, uint32_t addr) {
    asm volatile("ldmatrix.sync.aligned.m8n8.x4.shared.b16 {%0,%1,%2,%3}, [%4];"
                 : "=r"(r[0]), "=r"(r[1]), "=r"(r[2]), "=r"(r[3]) : "r"(addr));
}
__device__ __forceinline__ void mma16816(float* d, const uint32_t* a, const uint32_t* b) {
    asm volatile("mma.sync.aligned.m16n8k16.row.col.f32.bf16.bf16.f32 "
                 "{%0,%1,%2,%3}, {%4,%5,%6,%7}, {%8,%9}, {%0,%1,%2,%3};"
                 : "+f"(d[0]), "+f"(d[1]), "+f"(d[2]), "+f"(d[3])
                 : "r"(a[0]), "r"(a[1]), "r"(a[2]), "r"(a[3]), "r"(b[0]), "r"(b[1]));
}
__device__ __forceinline__ void split4(float4 v, uint32_t& h0, uint32_t& h1, uint32_t& l0, uint32_t& l1) {
    __nv_bfloat16 hx = __float2bfloat16(v.x), hy = __float2bfloat16(v.y);
    __nv_bfloat16 hz = __float2bfloat16(v.z), hw = __float2bfloat16(v.w);
    __nv_bfloat16 lx = __float2bfloat16(v.x - __bfloat162float(hx));
    __nv_bfloat16 ly = __float2bfloat16(v.y - __bfloat162float(hy));
    __nv_bfloat16 lz = __float2bfloat16(v.z - __bfloat162float(hz));
    __nv_bfloat16 lw = __float2bfloat16(v.w - __bfloat162float(hw));
    h0 = (uint32_t)__bfloat16_as_ushort(hx) | ((uint32_t)__bfloat16_as_ushort(hy) << 16);
    h1 = (uint32_t)__bfloat16_as_ushort(hz) | ((uint32_t)__bfloat16_as_ushort(hw) << 16);
    l0 = (uint32_t)__bfloat16_as_ushort(lx) | ((uint32_t)__bfloat16_as_ushort(ly) << 16);
    l1 = (uint32_t)__bfloat16_as_ushort(lz) | ((uint32_t)__bfloat16_as_ushort(lw) << 16);
}
__device__ __forceinline__ float sigf(float x) { return 1.f / (1.f + __expf(-x)); }

// ======================= device scratch =======================
__device__ __align__(16) float g_h[(size_t)(SEQ + 1) * BB * HH];  // slab 0 = h0, slab t+1 = h after step t
__device__ __align__(16) float g_c[BB * HH];
__device__ __align__(16) float g_emb[HH];
__device__ __align__(16) float g_bcat[H4];                        // gate-major: [g*HH + j]
__device__ __align__(16) __nv_bfloat16 g_Wb_hi[(size_t)H4 * K2H]; // [n = g*HH+j][k] K-major
__device__ __align__(16) __nv_bfloat16 g_Wb_lo[(size_t)H4 * K2H];

// ======================= prep =======================
__global__ void prep_w(const float* __restrict__ Wih, const float* __restrict__ Whh,
                       const float* __restrict__ bih, const float* __restrict__ bhh) {
    int idx = blockIdx.x * blockDim.x + threadIdx.x;
    if (idx < H4 * K2H) {
        int n = idx / K2H, k = idx % K2H;
        float v = (k < HH) ? Wih[n * HH + k] : Whh[n * HH + (k - HH)];
        __nv_bfloat16 h = __float2bfloat16(v);
        g_Wb_hi[idx] = h;
        g_Wb_lo[idx] = __float2bfloat16(v - __bfloat162float(h));
    }
    if (idx < H4) g_bcat[idx] = bih[idx] + bhh[idx];
}
__global__ void emb_kernel(const float* __restrict__ st, const float* __restrict__ W_emb,
                           const float* __restrict__ b_emb) {
    int j = threadIdx.x;
    float s = b_emb[j];
    #pragma unroll 8
    for (int k = 0; k < OO; k++) s += st[k] * W_emb[j * OO + k];
    g_emb[j] = s;
}

// ======================= init: h0/c0 (fp32, small) =======================
__global__ void __launch_bounds__(256) init_kernel(
    const float* __restrict__ eh, const float* __restrict__ W1, const float* __restrict__ b1,
    const float* __restrict__ W2, const float* __restrict__ b2) {
    __shared__ float As[64][17], B1s[64][17], B2s[64][17];
    int m0 = blockIdx.y * 64, j0 = blockIdx.x * 64;
    int tid = threadIdx.x, tm = tid >> 4, tj = tid & 15;
    float acc1[4][4] = {}, acc2[4][4] = {};
    for (int k0 = 0; k0 < LL; k0 += 16) {
        int r = tid >> 2, c = (tid & 3) * 4;
        float4 va = *(const float4*)&eh[(m0 + r) * LL + k0 + c];
        As[r][c] = va.x; As[r][c+1] = va.y; As[r][c+2] = va.z; As[r][c+3] = va.w;
        float4 v1 = *(const float4*)&W1[(j0 + r) * LL + k0 + c];
        B1s[r][c] = v1.x; B1s[r][c+1] = v1.y; B1s[r][c+2] = v1.z; B1s[r][c+3] = v1.w;
        float4 v2 = *(const float4*)&W2[(j0 + r) * LL + k0 + c];
        B2s[r][c] = v2.x; B2s[r][c+1] = v2.y; B2s[r][c+2] = v2.z; B2s[r][c+3] = v2.w;
        __syncthreads();
        #pragma unroll
        for (int kk = 0; kk < 16; kk++) {
            float a[4], u[4], v[4];
            #pragma unroll
            for (int i = 0; i < 4; i++) a[i] = As[tm * 4 + i][kk];
            #pragma unroll
            for (int jv = 0; jv < 4; jv++) { u[jv] = B1s[tj + jv * 16][kk]; v[jv] = B2s[tj + jv * 16][kk]; }
            #pragma unroll
            for (int i = 0; i < 4; i++)
                #pragma unroll
                for (int jv = 0; jv < 4; jv++) { acc1[i][jv] += a[i] * u[jv]; acc2[i][jv] += a[i] * v[jv]; }
        }
        __syncthreads();
    }
    #pragma unroll
    for (int i = 0; i < 4; i++)
        #pragma unroll
        for (int jv = 0; jv < 4; jv++) {
            int m = m0 + tm * 4 + i, j = j0 + tj + jv * 16;
            float h0 = acc1[i][jv] + b1[j]; h0 = h0 > 0.f ? h0 : 0.01f * h0;
            float c0 = acc2[i][jv] + b2[j]; c0 = c0 > 0.f ? c0 : 0.01f * c0;
            g_c[m * HH + j] = c0;
            g_h[(size_t)m * HH + j] = h0;
        }
}

// ======================= step: warp-MMA bf16-split GEMM + fused LSTM pointwise =======================
// CTA tile: M=128 x J=32 x 4 gates. Grid (512/32=16, 1024/128=8). 8 warps: wm=wid>>1 (m), wj=wid&1 (j).
// SMEM: [buf][ A_hi | A_lo | B_hi | B_lo ], each 128 rows x 32 k bf16, padded row stride 40 elems (80 B).
#define SA_H 0
#define SA_L 10240
#define SB_H 20480
#define SB_L 30720
#define SBUF 40960
#define SSM  81920

struct LdRegs { float4 aR[4]; uint4 bRh[2]; uint4 bRl[2]; };

__device__ __forceinline__ void load_chunk(int t, const float* __restrict__ hp,
                                           int m0, int j0, int k0, int tid, LdRegs& R) {
    #pragma unroll
    for (int i = 0; i < 4; i++) {
        int idx = tid + i * 256, r = idx >> 3, cg = idx & 7;
        int gk = k0 + cg * 4;
        float4 v;
        if (gk < HH) {  // relu(x) side
            v = (t == 0) ? *(const float4*)&g_emb[gk]
                         : *(const float4*)&hp[(size_t)(m0 + r) * HH + gk];
            v.x = fmaxf(v.x, 0.f); v.y = fmaxf(v.y, 0.f); v.z = fmaxf(v.z, 0.f); v.w = fmaxf(v.w, 0.f);
        } else {        // h side
            v = *(const float4*)&hp[(size_t)(m0 + r) * HH + gk - HH];
        }
        R.aR[i] = v;
    }
    #pragma unroll
    for (int i = 0; i < 2; i++) {
        int idx = tid + i * 256, r = idx >> 2, q = idx & 3;
        int n = (r >> 5) * HH + j0 + (r & 31);  // gate = r>>5, jj = r&31
        size_t go = (size_t)n * K2H + k0 + q * 8;
        R.bRh[i] = *(const uint4*)(g_Wb_hi + go);
        R.bRl[i] = *(const uint4*)(g_Wb_lo + go);
    }
}

__device__ __forceinline__ void store_chunk(char* base, int tid, const LdRegs& R) {
    #pragma unroll
    for (int i = 0; i < 4; i++) {
        int idx = tid + i * 256, r = idx >> 3, cg = idx & 7;
        uint32_t h0, h1, l0, l1;
        split4(R.aR[i], h0, h1, l0, l1);
        uint32_t off = (uint32_t)r * 80 + (uint32_t)cg * 8;
        *(uint2*)(base + SA_H + off) = make_uint2(h0, h1);
        *(uint2*)(base + SA_L + off) = make_uint2(l0, l1);
    }
    #pragma unroll
    for (int i = 0; i < 2; i++) {
        int idx = tid + i * 256, r = idx >> 2, q = idx & 3;
        uint32_t off = (uint32_t)r * 80 + (uint32_t)q * 16;
        *(uint4*)(base + SB_H + off) = R.bRh[i];
        *(uint4*)(base + SB_L + off) = R.bRl[i];
    }
}

__global__ void __launch_bounds__(256, 1) step_mma(int t) {
    extern __shared__ char sm[];
    uint32_t sb = smem_u32(sm);
    int tid = threadIdx.x, lane = tid & 31, wid = tid >> 5;
    int wm = wid >> 1, wj = wid & 1;
    int j0 = blockIdx.x * 32, m0 = blockIdx.y * 128;
    const float* __restrict__ hp = g_h + (size_t)t * (BB * HH);

    float acc[4][2][2][4];
    #pragma unroll
    for (int g = 0; g < 4; g++)
        #pragma unroll
        for (int i = 0; i < 2; i++)
            #pragma unroll
            for (int jn = 0; jn < 2; jn++)
                #pragma unroll
                for (int q = 0; q < 4; q++) acc[g][i][jn][q] = 0.f;

    LdRegs R;
    load_chunk(t, hp, m0, j0, 0, tid, R);

    for (int c = 0; c < 32; c++) {
        store_chunk(sm + (c & 1) * SBUF, tid, R);
        __syncthreads();
        if (c < 31) load_chunk(t, hp, m0, j0, (c + 1) * 32, tid, R);

        uint32_t sa = sb + (uint32_t)(c & 1) * SBUF;
        #pragma unroll
        for (int kk = 0; kk < 32; kk += 16) {
            uint32_t ah[2][4], al[2][4];
            #pragma unroll
            for (int i = 0; i < 2; i++) {
                uint32_t ad = sa + SA_H
                            + (uint32_t)(wm * 32 + i * 16 + (lane & 15)) * 80
                            + (uint32_t)(kk + (lane >> 4) * 8) * 2;
                ldm_x4(ah[i], ad);
                ldm_x4(al[i], ad + (SA_L - SA_H));
            }
            #pragma unroll
            for (int g = 0; g < 4; g++) {
                uint32_t bh[4], bl[4];
                uint32_t bd = sa + SB_H
                            + (uint32_t)(g * 32 + wj * 16 + (lane >> 4) * 8 + (lane & 7)) * 80
                            + (uint32_t)(kk + ((lane >> 3) & 1) * 8) * 2;
                ldm_x4(bh, bd);
                ldm_x4(bl, bd + (SB_L - SB_H));
                #pragma unroll
                for (int i = 0; i < 2; i++)
                    #pragma unroll
                    for (int jn = 0; jn < 2; jn++) {
                        mma16816(acc[g][i][jn], ah[i], &bh[jn * 2]);
                        mma16816(acc[g][i][jn], ah[i], &bl[jn * 2]);
                        mma16816(acc[g][i][jn], al[i], &bh[jn * 2]);
                    }
            }
        }
    }

    // fused LSTM pointwise epilogue — each thread owns all 4 gates for its (m, j)
    float* __restrict__ hn = g_h + (size_t)(t + 1) * (BB * HH);
    #pragma unroll
    for (int i = 0; i < 2; i++)
        #pragma unroll
        for (int rr = 0; rr < 2; rr++) {
            int m = m0 + wm * 32 + i * 16 + (lane >> 2) + rr * 8;
            #pragma unroll
            for (int jn = 0; jn < 2; jn++)
                #pragma unroll
                for (int cc = 0; cc < 2; cc++) {
                    int j = j0 + wj * 16 + jn * 8 + (lane & 3) * 2 + cc;
                    int q = rr * 2 + cc;
                    float gi = acc[0][i][jn][q] + g_bcat[0 * HH + j];
                    float gf = acc[1][i][jn][q] + g_bcat[1 * HH + j];
                    float gg = acc[2][i][jn][q] + g_bcat[2 * HH + j];
                    float go = acc[3][i][jn][q] + g_bcat[3 * HH + j];
                    size_t o = (size_t)m * HH + j;
                    float cn = sigf(gf) * g_c[o] + sigf(gi) * tanhf(gg);
                    g_c[o] = cn;
                    hn[o] = sigf(go) * tanhf(cn);
                }
        }
}

// ======================= y projection (fp32) =======================
__global__ void __launch_bounds__(256) y_kernel(const float* __restrict__ W_out,
                                                const float* __restrict__ b_out,
                                                float* __restrict__ out_dec) {
    __shared__ float As[64][17];
    __shared__ float Bs[128][17];
    int t = blockIdx.y;
    int m0 = blockIdx.x * 64;
    int tid = threadIdx.x, tm = tid >> 4, to = tid & 15;
    const float* __restrict__ hsrc = &g_h[(size_t)(t + 1) * (BB * HH)];
    float acc[4][8] = {};
    for (int k0 = 0; k0 < HH; k0 += 16) {
        {
            int r = tid >> 2, c = (tid & 3) * 4;
            float4 v = *(const float4*)&hsrc[(m0 + r) * HH + k0 + c];
            As[r][c] = v.x; As[r][c+1] = v.y; As[r][c+2] = v.z; As[r][c+3] = v.w;
        }
        #pragma unroll
        for (int q = 0; q < 2; q++) {
            int idx = tid + q * 256;
            int r = idx >> 2, c = (idx & 3) * 4;
            float4 v = *(const float4*)&W_out[r * HH + k0 + c];
            Bs[r][c] = v.x; Bs[r][c+1] = v.y; Bs[r][c+2] = v.z; Bs[r][c+3] = v.w;
        }
        __syncthreads();
        #pragma unroll
        for (int kk = 0; kk < 16; kk++) {
            float a[4], b[8];
            #pragma unroll
            for (int i = 0; i < 4; i++) a[i] = As[tm * 4 + i][kk];
            #pragma unroll
            for (int oi = 0; oi < 8; oi++) b[oi] = Bs[to + oi * 16][kk];
            #pragma unroll
            for (int i = 0; i < 4; i++)
                #pragma unroll
                for (int oi = 0; oi < 8; oi++) acc[i][oi] += a[i] * b[oi];
        }
        __syncthreads();
    }
    #pragma unroll
    for (int i = 0; i < 4; i++)
        #pragma unroll
        for (int oi = 0; oi < 8; oi++) {
            int m = m0 + tm * 4 + i, o = to + oi * 16;
            out_dec[((size_t)m * SEQ + t) * OO + o] = acc[i][oi] + b_out[o];
        }
}

__global__ void hc_kernel(float* __restrict__ out_h, float* __restrict__ out_c) {
    int i = blockIdx.x * blockDim.x + threadIdx.x;
    if (i < BB * HH) {
        out_h[i] = g_h[(size_t)SEQ * (BB * HH) + i];
        out_c[i] = g_c[i];
    }
}

// ======================= num head (fp32 fused, round-1 proven) =======================
__global__ void __launch_bounds__(256) num_kernel(
    const float* __restrict__ E, const float* __restrict__ Wseq, const float* __restrict__ bseq,
    const float* __restrict__ w2, const float* __restrict__ b2, float* __restrict__ outnum) {
    __shared__ float As[64][17], Bs[64][17];
    __shared__ float P[64][17];
    int m0 = blockIdx.x * 64;
    int tid = threadIdx.x, tm = tid >> 4, tj = tid & 15;
    float part[4] = {0.f, 0.f, 0.f, 0.f};
    for (int j0 = 0; j0 < HH; j0 += 64) {
        float acc[4][4] = {};
        for (int k0 = 0; k0 < LL; k0 += 16) {
            int r = tid >> 2, c = (tid & 3) * 4;
            float4 va = *(const float4*)&E[((size_t)(m0 + r)) * LL + k0 + c];
            As[r][c] = va.x; As[r][c+1] = va.y; As[r][c+2] = va.z; As[r][c+3] = va.w;
            float4 vb = *(const float4*)&Wseq[(j0 + r) * LL + k0 + c];
            Bs[r][c] = vb.x; Bs[r][c+1] = vb.y; Bs[r][c+2] = vb.z; Bs[r][c+3] = vb.w;
            __syncthreads();
            #pragma unroll
            for (int kk = 0; kk < 16; kk++) {
                float a[4], b[4];
                #pragma unroll
                for (int i = 0; i < 4; i++) a[i] = As[tm * 4 + i][kk];
                #pragma unroll
                for (int jv = 0; jv < 4; jv++) b[jv] = Bs[tj + jv * 16][kk];
                #pragma unroll
                for (int i = 0; i < 4; i++)
                    #pragma unroll
                    for (int jv = 0; jv < 4; jv++) acc[i][jv] += a[i] * b[jv];
            }
            __syncthreads();
        }
        #pragma unroll
        for (int i = 0; i < 4; i++)
            #pragma unroll
            for (int jv = 0; jv < 4; jv++) {
                int j = j0 + tj + jv * 16;
                float v = acc[i][jv] + bseq[j];
                v = v > 0.f ? v : 0.01f * v;
                part[i] += v * w2[j];
            }
    }
    #pragma unroll
    for (int i = 0; i < 4; i++) P[tm * 4 + i][tj] = part[i];
    __syncthreads();
    if (tid < 64) {
        float s = 0.f;
        #pragma unroll
        for (int q = 0; q < 16; q++) s += P[tid][q];
        float v = s + b2[0];
        outnum[m0 + tid] = v > 0.f ? v : 0.f;
    }
}

// ======================= launch =======================
extern "C" void kernel_launch(void* const* d_in, const int* in_sizes, int n_in,
                              void* d_out, int out_size) {
    const float* enc_out = (const float*)d_in[0];
    const float* enc_hid = (const float*)d_in[1];
    const float* start   = (const float*)d_in[2];
    const float* W1   = (const float*)d_in[3];
    const float* b1   = (const float*)d_in[4];
    const float* W2   = (const float*)d_in[5];
    const float* b2   = (const float*)d_in[6];
    const float* Wemb = (const float*)d_in[7];
    const float* bemb = (const float*)d_in[8];
    const float* Wih  = (const float*)d_in[9];
    const float* Whh  = (const float*)d_in[10];
    const float* bih  = (const float*)d_in[11];
    const float* bhh  = (const float*)d_in[12];
    const float* Wout = (const float*)d_in[13];
    const float* bout = (const float*)d_in[14];
    const float* Wseq = (const float*)d_in[15];
    const float* bseq = (const float*)d_in[16];
    const float* Wsq2 = (const float*)d_in[17];
    const float* bsq2 = (const float*)d_in[18];
    // d_in[19] = seq_len (constant 100; hardcoded)

    float* out = (float*)d_out;
    float* out_dec = out;                           // [B, SEQ, O]
    float* out_h   = out + (size_t)BB * SEQ * OO;   // [1, B, H]
    float* out_c   = out_h + (size_t)BB * HH;       // [1, B, H]
    float* out_num = out_c + (size_t)BB * HH;       // [B, TENC, 1]

    cudaFuncSetAttribute(step_mma, cudaFuncAttributeMaxDynamicSharedMemorySize, SSM);

    prep_w<<<(H4 * K2H + 255) / 256, 256>>>(Wih, Whh, bih, bhh);
    emb_kernel<<<1, HH>>>(start, Wemb, bemb);
    init_kernel<<<dim3(HH / 64, BB / 64), 256>>>(enc_hid, W1, b1, W2, b2);

    for (int t = 0; t < SEQ; t++)
        step_mma<<<dim3(16, 8), 256, SSM>>>(t);

    y_kernel<<<dim3(BB / 64, SEQ), 256>>>(Wout, bout, out_dec);
    hc_kernel<<<(BB * HH + 255) / 256, 256>>>(out_h, out_c);
    num_kernel<<<BTENC / 64, 256>>>(enc_out, Wseq, bseq, Wsq2, bsq2, out_num);
}